// round 2
// baseline (speedup 1.0000x reference)
#include <cuda_runtime.h>

#define NN 100000
#define EE 800000
#define HH 128
#define GG 64
#define LL 4

typedef unsigned long long ull;

// ------------------ static device scratch (no allocation) ------------------
__device__ float g_h[(size_t)NN * HH];
__device__ float g_u[(size_t)NN * HH];
__device__ float g_z[(size_t)NN * HH];
__device__ int   g_deg[NN];
__device__ int   g_rowptr[NN + 1];
__device__ int   g_cur[NN];
__device__ int   g_colidx[2 * EE];
__device__ float g_colsum[HH];
__device__ float g_colsq[HH];
__device__ __align__(16) float g_bnscale[HH];
__device__ __align__(16) float g_bnshift[HH];
__device__ float g_pool[GG * HH];
__device__ float g_cnt[GG];

// ------------------ f32x2 packed FMA helpers (sm_103a) ------------------
__device__ __forceinline__ void ffma2(ull& d, ull a, ull b) {
    asm("fma.rn.f32x2 %0, %1, %2, %0;" : "+l"(d) : "l"(a), "l"(b));
}
__device__ __forceinline__ float f2sum(ull p) {
    float lo, hi;
    asm("mov.b64 {%0, %1}, %2;" : "=f"(lo), "=f"(hi) : "l"(p));
    return lo + hi;
}

constexpr int ASTR = 132;                                  // padded A stride (floats)
constexpr int SMEM_GEMM = (64 * ASTR + 128 * 128) * 4;     // 99328 B

// ------------------ fused 64x128x128 GEMM ------------------
// MODE 0: C = A@W + b
// MODE 1: C = A@W + b, accumulate per-column sum/sumsq into g_colsum/g_colsq
// MODE 2: A' = relu(A*bnscale+bnshift); C = LayerNorm(C + relu(A'@W + b))  (C==g_h)
template <int MODE>
__global__ void __launch_bounds__(256, 2) gemm128(
    const float* __restrict__ A, const float* __restrict__ W,
    const float* __restrict__ bias, float* __restrict__ C,
    const float* __restrict__ lng, const float* __restrict__ lnb)
{
    extern __shared__ float sm[];
    float* As = sm;               // [64][ASTR]
    float* Bs = sm + 64 * ASTR;   // [n][k^swz]

    const int tid = threadIdx.x;
    const int row0 = blockIdx.x * 64;

    // W (128x128) -> Bs transposed + swizzled
#pragma unroll
    for (int i = 0; i < 16; i++) {
        int f = i * 256 + tid;
        int k = f >> 5;
        int n4 = f & 31;                      // columns n4*4 .. n4*4+3
        float4 v = __ldg((const float4*)W + f);
        int ks = k ^ (((n4 >> 1) & 15) << 1); // swz(n) = (n>>3)<<1
        Bs[(n4 * 4 + 0) * 128 + ks] = v.x;
        Bs[(n4 * 4 + 1) * 128 + ks] = v.y;
        Bs[(n4 * 4 + 2) * 128 + ks] = v.z;
        Bs[(n4 * 4 + 3) * 128 + ks] = v.w;
    }
    // A tile (64x128) -> As, MODE2 applies BN-scale + ReLU on the fly
#pragma unroll
    for (int i = 0; i < 8; i++) {
        int f = i * 256 + tid;
        int m = f >> 5;
        int k4 = f & 31;
        int row = row0 + m;
        float4 v = make_float4(0.f, 0.f, 0.f, 0.f);
        if (row < NN) v = __ldg((const float4*)(A + (size_t)row * HH) + k4);
        if (MODE == 2) {
            float4 sc = *((const float4*)g_bnscale + k4);
            float4 sh = *((const float4*)g_bnshift + k4);
            v.x = fmaxf(fmaf(v.x, sc.x, sh.x), 0.f);
            v.y = fmaxf(fmaf(v.y, sc.y, sh.y), 0.f);
            v.z = fmaxf(fmaf(v.z, sc.z, sh.z), 0.f);
            v.w = fmaxf(fmaf(v.w, sc.w, sh.w), 0.f);
        }
        *(float4*)(As + m * ASTR + k4 * 4) = v;
    }
    __syncthreads();

    const int cg = tid & 15;   // cols cg*8 .. cg*8+7
    const int rg = tid >> 4;   // rows rg*4 .. rg*4+3
    const float* Ap = As + rg * 4 * ASTR;
    const float* Bp = Bs + cg * 8 * 128;
    const int sw = cg << 1;

    ull acc[4][8];
#pragma unroll
    for (int j = 0; j < 4; j++)
#pragma unroll
        for (int q = 0; q < 8; q++) acc[j][q] = 0ull;

#pragma unroll 8
    for (int kk = 0; kk < 128; kk += 2) {
        int ks = kk ^ sw;
        ull bb[8];
#pragma unroll
        for (int q = 0; q < 8; q++) bb[q] = *(const ull*)(Bp + q * 128 + ks);
        ull aa[4];
#pragma unroll
        for (int j = 0; j < 4; j++) aa[j] = *(const ull*)(Ap + j * ASTR + kk);
#pragma unroll
        for (int j = 0; j < 4; j++)
#pragma unroll
            for (int q = 0; q < 8; q++) ffma2(acc[j][q], aa[j], bb[q]);
    }

    float bv[8];
    {
        float4 t0 = __ldg((const float4*)bias + cg * 2);
        float4 t1 = __ldg((const float4*)bias + cg * 2 + 1);
        bv[0] = t0.x; bv[1] = t0.y; bv[2] = t0.z; bv[3] = t0.w;
        bv[4] = t1.x; bv[5] = t1.y; bv[6] = t1.z; bv[7] = t1.w;
    }

    if (MODE != 2) {
        float ps[8], pq[8];
#pragma unroll
        for (int q = 0; q < 8; q++) { ps[q] = 0.f; pq[q] = 0.f; }
#pragma unroll
        for (int j = 0; j < 4; j++) {
            int row = row0 + rg * 4 + j;
            if (row < NN) {
                float o[8];
#pragma unroll
                for (int q = 0; q < 8; q++) o[q] = f2sum(acc[j][q]) + bv[q];
                float* cp = C + (size_t)row * HH + cg * 8;
                *(float4*)cp = make_float4(o[0], o[1], o[2], o[3]);
                *(float4*)(cp + 4) = make_float4(o[4], o[5], o[6], o[7]);
                if (MODE == 1) {
#pragma unroll
                    for (int q = 0; q < 8; q++) { ps[q] += o[q]; pq[q] += o[q] * o[q]; }
                }
            }
        }
        if (MODE == 1) {
            __syncthreads();                 // done with As/Bs
            float* ssum = sm;
            float* ssq = sm + 128;
            if (tid < 128) { ssum[tid] = 0.f; ssq[tid] = 0.f; }
            __syncthreads();
#pragma unroll
            for (int q = 0; q < 8; q++) {
                atomicAdd(&ssum[cg * 8 + q], ps[q]);
                atomicAdd(&ssq[cg * 8 + q], pq[q]);
            }
            __syncthreads();
            if (tid < 128) {
                atomicAdd(&g_colsum[tid], ssum[tid]);
                atomicAdd(&g_colsq[tid], ssq[tid]);
            }
        }
    } else {
        float lg[8], lb[8];
        {
            float4 t0 = __ldg((const float4*)lng + cg * 2);
            float4 t1 = __ldg((const float4*)lng + cg * 2 + 1);
            lg[0] = t0.x; lg[1] = t0.y; lg[2] = t0.z; lg[3] = t0.w;
            lg[4] = t1.x; lg[5] = t1.y; lg[6] = t1.z; lg[7] = t1.w;
            float4 u0 = __ldg((const float4*)lnb + cg * 2);
            float4 u1 = __ldg((const float4*)lnb + cg * 2 + 1);
            lb[0] = u0.x; lb[1] = u0.y; lb[2] = u0.z; lb[3] = u0.w;
            lb[4] = u1.x; lb[5] = u1.y; lb[6] = u1.z; lb[7] = u1.w;
        }
#pragma unroll
        for (int j = 0; j < 4; j++) {
            int row = row0 + rg * 4 + j;
            bool valid = (row < NN);
            float4 h0 = make_float4(0.f, 0.f, 0.f, 0.f), h1 = h0;
            float* hp = C + (size_t)row * HH + cg * 8;
            if (valid) { h0 = *(float4*)hp; h1 = *(float4*)(hp + 4); }
            float t[8];
            t[0] = h0.x + fmaxf(f2sum(acc[j][0]) + bv[0], 0.f);
            t[1] = h0.y + fmaxf(f2sum(acc[j][1]) + bv[1], 0.f);
            t[2] = h0.z + fmaxf(f2sum(acc[j][2]) + bv[2], 0.f);
            t[3] = h0.w + fmaxf(f2sum(acc[j][3]) + bv[3], 0.f);
            t[4] = h1.x + fmaxf(f2sum(acc[j][4]) + bv[4], 0.f);
            t[5] = h1.y + fmaxf(f2sum(acc[j][5]) + bv[5], 0.f);
            t[6] = h1.z + fmaxf(f2sum(acc[j][6]) + bv[6], 0.f);
            t[7] = h1.w + fmaxf(f2sum(acc[j][7]) + bv[7], 0.f);
            float s = 0.f, sq = 0.f;
#pragma unroll
            for (int q = 0; q < 8; q++) { s += t[q]; sq += t[q] * t[q]; }
            // row spans 16 consecutive lanes (same rg) -> reduce within 16-lane group
#pragma unroll
            for (int m = 1; m < 16; m <<= 1) {
                s  += __shfl_xor_sync(0xFFFFFFFFu, s, m);
                sq += __shfl_xor_sync(0xFFFFFFFFu, sq, m);
            }
            float mean = s * (1.0f / 128.0f);
            float var = sq * (1.0f / 128.0f) - mean * mean;
            float r = rsqrtf(var + 1e-5f);
            if (valid) {
                float o[8];
#pragma unroll
                for (int q = 0; q < 8; q++) o[q] = (t[q] - mean) * r * lg[q] + lb[q];
                *(float4*)hp = make_float4(o[0], o[1], o[2], o[3]);
                *(float4*)(hp + 4) = make_float4(o[4], o[5], o[6], o[7]);
            }
        }
    }
}

// ------------------ graph preprocessing ------------------
__global__ void initk() {
    int i = blockIdx.x * blockDim.x + threadIdx.x;
    if (i < NN) g_deg[i] = 0;
    if (i < GG * HH) g_pool[i] = 0.f;
    if (i < GG) g_cnt[i] = 0.f;
    if (i < HH) { g_colsum[i] = 0.f; g_colsq[i] = 0.f; }
}

__global__ void degk(const int* __restrict__ ei) {
    int e = blockIdx.x * blockDim.x + threadIdx.x;
    if (e >= EE) return;
    int r = ei[e], c = ei[EE + e];
    if (r != c) { atomicAdd(&g_deg[r], 1); atomicAdd(&g_deg[c], 1); }
}

__global__ void scank() {
    const int tid = threadIdx.x;
    const int lane = tid & 31, wid = tid >> 5;
    __shared__ int wsum[32];
    __shared__ int s_carry;
    if (tid == 0) s_carry = 0;
    __syncthreads();
    for (int base = 0; base < NN; base += 1024) {
        int i = base + tid;
        int v = (i < NN) ? g_deg[i] : 0;
        int x = v;
#pragma unroll
        for (int d = 1; d < 32; d <<= 1) {
            int y = __shfl_up_sync(0xFFFFFFFFu, x, d);
            if (lane >= d) x += y;
        }
        if (lane == 31) wsum[wid] = x;
        __syncthreads();
        if (wid == 0) {
            int w = wsum[lane];
#pragma unroll
            for (int d = 1; d < 32; d <<= 1) {
                int y = __shfl_up_sync(0xFFFFFFFFu, w, d);
                if (lane >= d) w += y;
            }
            wsum[lane] = w;
        }
        __syncthreads();
        int carry = s_carry;
        int excl = carry + (wid > 0 ? wsum[wid - 1] : 0) + x - v;
        if (i < NN) { g_rowptr[i] = excl; g_cur[i] = excl; }
        __syncthreads();
        if (tid == 0) s_carry = carry + wsum[31];
        __syncthreads();
    }
    if (tid == 0) g_rowptr[NN] = s_carry;
}

__global__ void fillk(const int* __restrict__ ei) {
    int e = blockIdx.x * blockDim.x + threadIdx.x;
    if (e >= EE) return;
    int r = ei[e], c = ei[EE + e];
    if (r != c) {
        int p = atomicAdd(&g_cur[r], 1); g_colidx[p] = c;
        int q = atomicAdd(&g_cur[c], 1); g_colidx[q] = r;
    }
}

// ------------------ GIN aggregation: one warp per node ------------------
__global__ void aggk(const float* __restrict__ h, float* __restrict__ u,
                     const float* __restrict__ eps_l, int layer) {
    int w = (blockIdx.x * blockDim.x + threadIdx.x) >> 5;
    if (w >= NN) return;
    int lane = threadIdx.x & 31;
    float e1 = 1.0f + __ldg(eps_l + layer);
    const float4* hp = (const float4*)h;
    float4 a = __ldg(hp + (size_t)w * 32 + lane);
    float4 acc = make_float4(a.x * e1, a.y * e1, a.z * e1, a.w * e1);
    int beg = g_rowptr[w], end = g_rowptr[w + 1];
    for (int e = beg; e < end; e++) {
        int nb = g_colidx[e];
        float4 v = __ldg(hp + (size_t)nb * 32 + lane);
        acc.x += v.x; acc.y += v.y; acc.z += v.z; acc.w += v.w;
    }
    ((float4*)u)[(size_t)w * 32 + lane] = acc;
}

// ------------------ BN parameter fold (and reset stats) ------------------
__global__ void bnparamsk(const float* __restrict__ bng, const float* __restrict__ bnb) {
    int f = threadIdx.x;  // 128 threads
    float m = g_colsum[f] * (1.0f / NN);
    float v = g_colsq[f] * (1.0f / NN) - m * m;
    float sc = __ldg(bng + f) * rsqrtf(v + 1e-5f);
    g_bnscale[f] = sc;
    g_bnshift[f] = __ldg(bnb + f) - m * sc;
    g_colsum[f] = 0.f;
    g_colsq[f] = 0.f;
}

// ------------------ pooling (batch is sorted) ------------------
__global__ void poolk(const float* __restrict__ h, const int* __restrict__ batch) {
    int f = threadIdx.x;  // 128 threads
    int chunk = (NN + gridDim.x - 1) / gridDim.x;
    int s = blockIdx.x * chunk;
    int e = s + chunk; if (e > NN) e = NN;
    if (s >= e) return;
    int g = __ldg(batch + s);
    float acc = 0.f, cnt = 0.f;
    for (int n = s; n < e; n++) {
        int bg = __ldg(batch + n);
        if (bg != g) {
            atomicAdd(&g_pool[g * HH + f], acc);
            if (f == 0) atomicAdd(&g_cnt[g], cnt);
            acc = 0.f; cnt = 0.f; g = bg;
        }
        acc += h[(size_t)n * HH + f];
        cnt += 1.f;
    }
    atomicAdd(&g_pool[g * HH + f], acc);
    if (f == 0) atomicAdd(&g_cnt[g], cnt);
}

__global__ void finalk(float* __restrict__ out) {
    int i = blockIdx.x * blockDim.x + threadIdx.x;
    if (i < GG * HH) {
        float c = g_cnt[i >> 7];
        out[i] = g_pool[i] / fmaxf(c, 1.0f);
    }
}

// ------------------ host launcher ------------------
extern "C" void kernel_launch(void* const* d_in, const int* in_sizes, int n_in,
                              void* d_out, int out_size) {
    const float* x     = (const float*)d_in[0];
    const float* W0    = (const float*)d_in[1];
    const float* b0    = (const float*)d_in[2];
    const float* eps_l = (const float*)d_in[3];
    const float* W1    = (const float*)d_in[4];
    const float* b1    = (const float*)d_in[5];
    const float* bng   = (const float*)d_in[6];
    const float* bnb   = (const float*)d_in[7];
    const float* W2    = (const float*)d_in[8];
    const float* b2    = (const float*)d_in[9];
    const float* lng   = (const float*)d_in[10];
    const float* lnb   = (const float*)d_in[11];
    const int*   ei    = (const int*)d_in[12];
    const int*   batch = (const int*)d_in[13];
    float* out = (float*)d_out;

    cudaFuncSetAttribute((const void*)gemm128<0>, cudaFuncAttributeMaxDynamicSharedMemorySize, SMEM_GEMM);
    cudaFuncSetAttribute((const void*)gemm128<1>, cudaFuncAttributeMaxDynamicSharedMemorySize, SMEM_GEMM);
    cudaFuncSetAttribute((const void*)gemm128<2>, cudaFuncAttributeMaxDynamicSharedMemorySize, SMEM_GEMM);

    float *ph, *pu, *pz;
    cudaGetSymbolAddress((void**)&ph, g_h);
    cudaGetSymbolAddress((void**)&pu, g_u);
    cudaGetSymbolAddress((void**)&pz, g_z);

    const int GB = (NN + 63) / 64;  // 1563 gemm blocks
    initk<<<(NN + 255) / 256, 256>>>();
    degk<<<(EE + 255) / 256, 256>>>(ei);
    scank<<<1, 1024>>>();
    fillk<<<(EE + 255) / 256, 256>>>(ei);

    gemm128<0><<<GB, 256, SMEM_GEMM>>>(x, W0, b0, ph, nullptr, nullptr);

    for (int i = 0; i < LL; i++) {
        aggk<<<(NN * 32 + 255) / 256, 256>>>(ph, pu, eps_l, i);
        gemm128<1><<<GB, 256, SMEM_GEMM>>>(pu, W1 + i * HH * HH, b1 + i * HH, pz, nullptr, nullptr);
        bnparamsk<<<1, 128>>>(bng + i * HH, bnb + i * HH);
        gemm128<2><<<GB, 256, SMEM_GEMM>>>(pz, W2 + i * HH * HH, b2 + i * HH, ph, lng + i * HH, lnb + i * HH);
    }

    poolk<<<500, 128>>>(ph, batch);
    finalk<<<(GG * HH + 255) / 256, 256>>>(out);
}

// round 4
// speedup vs baseline: 1.4454x; 1.4454x over previous
#include <cuda_runtime.h>
#include <cuda_bf16.h>

#define NN 100000
#define EE 800000
#define HH 128
#define GG 64
#define LL 4

typedef unsigned int u32;
typedef unsigned short u16;

// ------------------ static device scratch ------------------
__device__ float g_h[(size_t)NN * HH];
__device__ float g_u[(size_t)NN * HH];
__device__ float g_z[(size_t)NN * HH];
__device__ int   g_deg[NN];
__device__ int   g_rowptr[NN + 1];
__device__ int   g_cur[NN];
__device__ int   g_colidx[2 * EE];
__device__ int   g_bsum[128];
__device__ int   g_boff[128];
__device__ float g_colsum[HH];
__device__ float g_colsq[HH];
__device__ __align__(16) float g_bnscale[HH];
__device__ __align__(16) float g_bnshift[HH];
__device__ float g_pool[GG * HH];
__device__ float g_cnt[GG];
__device__ __align__(16) u16 g_wthi[9 * HH * HH];  // transposed [n][k] bf16 hi
__device__ __align__(16) u16 g_wtlo[9 * HH * HH];  // bf16 lo residual

// ------------------ PTX helpers ------------------
__device__ __forceinline__ u32 smem_u32(const void* p) {
    u32 a;
    asm("{ .reg .u64 t; cvta.to.shared.u64 t, %1; cvt.u32.u64 %0, t; }" : "=r"(a) : "l"(p));
    return a;
}
__device__ __forceinline__ void ldm4(u32 r[4], u32 addr) {
    asm volatile("ldmatrix.sync.aligned.m8n8.x4.shared.b16 {%0,%1,%2,%3}, [%4];"
                 : "=r"(r[0]), "=r"(r[1]), "=r"(r[2]), "=r"(r[3]) : "r"(addr));
}
__device__ __forceinline__ void mma16816(float* c, const u32 a[4], u32 b0, u32 b1) {
    asm volatile(
        "mma.sync.aligned.m16n8k16.row.col.f32.bf16.bf16.f32 "
        "{%0,%1,%2,%3}, {%4,%5,%6,%7}, {%8,%9}, {%0,%1,%2,%3};"
        : "+f"(c[0]), "+f"(c[1]), "+f"(c[2]), "+f"(c[3])
        : "r"(a[0]), "r"(a[1]), "r"(a[2]), "r"(a[3]), "r"(b0), "r"(b1));
}
__device__ __forceinline__ u32 packbf2(float x, float y) {
    __nv_bfloat162 t = __floats2bfloat162_rn(x, y);
    return *(u32*)&t;
}

// smem: tiles Ahi@0 Alo@16384 Bhi@32768 Blo@49152 (bytes) during mainloop;
// staging fp32 [128][132] @0 (floats 0..16891) in epilogue;
// params: bias @f16896, lng @f17024, lnb @f17152; total 17280 floats.
constexpr int SMEM_HM = 17280 * 4;   // 69120 B
constexpr int F_BIAS = 16896, F_LNG = 17024, F_LNB = 17152;

// ------------------ fused HMMA 3xbf16 GEMM: 128 rows x 128 cols per CTA ------------------
// MODE 0: C = A@W + b
// MODE 1: C = A@W + b, accumulate column sum/sumsq (BN stats)
// MODE 2: A' = relu(A*bnscale+bnshift); C = LayerNorm(C + relu(A'@W + b))
template <int MODE>
__global__ void __launch_bounds__(256, 2) gemm_hmma(
    const float* __restrict__ A, const u16* __restrict__ Whi, const u16* __restrict__ Wlo,
    const float* __restrict__ bias, float* __restrict__ C,
    const float* __restrict__ lng, const float* __restrict__ lnb)
{
    extern __shared__ float sm[];
    const u32 sb = smem_u32(sm);
    const int tid = threadIdx.x;
    const int lane = tid & 31, wid = tid >> 5;
    const int row0 = blockIdx.x * 128;

    if (tid < 128) {
        sm[F_BIAS + tid] = __ldg(bias + tid);
        if (MODE == 2) { sm[F_LNG + tid] = __ldg(lng + tid); sm[F_LNB + tid] = __ldg(lnb + tid); }
    }

    float c[16][4];
#pragma unroll
    for (int n = 0; n < 16; n++)
#pragma unroll
        for (int j = 0; j < 4; j++) c[n][j] = 0.f;

    for (int h = 0; h < 2; h++) {
        // ---- B tiles: 128n x 64k bf16 hi/lo, swizzled (16B chunk ^= n&7) ----
#pragma unroll
        for (int i = 0; i < 4; i++) {
            int f = i * 256 + tid;        // 1024 uint4
            int n = f >> 3, q = f & 7;
            uint4 vh = __ldg((const uint4*)(Whi + (size_t)n * HH + h * 64) + q);
            uint4 vl = __ldg((const uint4*)(Wlo + (size_t)n * HH + h * 64) + q);
            u32 off = (u32)(n * 128 + ((q ^ (n & 7)) << 4));
            *(uint4*)((char*)sm + 32768 + off) = vh;
            *(uint4*)((char*)sm + 49152 + off) = vl;
        }
        // ---- A tile: 128 x 64 fp32 -> bf16 hi/lo split, swizzled ----
#pragma unroll
        for (int i = 0; i < 8; i++) {
            int f = i * 256 + tid;        // 2048 float4
            int r = f >> 4, c4 = f & 15;
            int row = row0 + r;
            float4 v = make_float4(0.f, 0.f, 0.f, 0.f);
            if (row < NN) v = __ldg((const float4*)(A + (size_t)row * HH + h * 64) + c4);
            if (MODE == 2) {
                float4 sc = ((const float4*)g_bnscale)[h * 16 + c4];
                float4 sh = ((const float4*)g_bnshift)[h * 16 + c4];
                v.x = fmaxf(fmaf(v.x, sc.x, sh.x), 0.f);
                v.y = fmaxf(fmaf(v.y, sc.y, sh.y), 0.f);
                v.z = fmaxf(fmaf(v.z, sc.z, sh.z), 0.f);
                v.w = fmaxf(fmaf(v.w, sc.w, sh.w), 0.f);
            }
            float hx = __bfloat162float(__float2bfloat16_rn(v.x));
            float hy = __bfloat162float(__float2bfloat16_rn(v.y));
            float hz = __bfloat162float(__float2bfloat16_rn(v.z));
            float hw = __bfloat162float(__float2bfloat16_rn(v.w));
            u32 off = (u32)(r * 128 + (((c4 >> 1) ^ (r & 7)) << 4) + (c4 & 1) * 8);
            *(uint2*)((char*)sm + off) = make_uint2(packbf2(v.x, v.y), packbf2(v.z, v.w)); // hi
            *(uint2*)((char*)sm + 16384 + off) =
                make_uint2(packbf2(v.x - hx, v.y - hy), packbf2(v.z - hz, v.w - hw));     // lo
        }
        __syncthreads();

        // ---- mainloop: 4 k-steps of 16 ----
        const int ar = (wid << 4) + (lane & 7) + (lane & 8);
        const int bq = ((lane >> 4) << 3) + (lane & 7);
#pragma unroll
        for (int s = 0; s < 4; s++) {
            int ach = 2 * s + (lane >> 4);
            u32 aoff = (u32)(ar * 128 + ((ach ^ (ar & 7)) << 4));
            u32 ah[4], al[4];
            ldm4(ah, sb + aoff);
            ldm4(al, sb + 16384 + aoff);
            int bch = 2 * s + ((lane >> 3) & 1);
#pragma unroll
            for (int n2 = 0; n2 < 8; n2++) {
                int bn = (n2 << 4) + bq;
                u32 boff = (u32)(bn * 128 + ((bch ^ (bn & 7)) << 4));
                u32 bh[4], bl[4];
                ldm4(bh, sb + 32768 + boff);
                ldm4(bl, sb + 49152 + boff);
                mma16816(c[2 * n2],     ah, bh[0], bh[1]);
                mma16816(c[2 * n2],     ah, bl[0], bl[1]);
                mma16816(c[2 * n2],     al, bh[0], bh[1]);
                mma16816(c[2 * n2 + 1], ah, bh[2], bh[3]);
                mma16816(c[2 * n2 + 1], ah, bl[2], bl[3]);
                mma16816(c[2 * n2 + 1], al, bh[2], bh[3]);
            }
        }
        __syncthreads();   // tiles free for next half / staging
    }

    // ---- stage C + bias into smem [128][132] fp32 ----
    {
        const int r0s = (wid << 4) + (lane >> 2);
#pragma unroll
        for (int n = 0; n < 16; n++) {
            int col = n * 8 + (lane & 3) * 2;
            float b0 = sm[F_BIAS + col], b1 = sm[F_BIAS + col + 1];
            *(float2*)&sm[r0s * 132 + col] = make_float2(c[n][0] + b0, c[n][1] + b1);
            *(float2*)&sm[(r0s + 8) * 132 + col] = make_float2(c[n][2] + b0, c[n][3] + b1);
        }
    }
    __syncthreads();

    if (MODE != 2) {
        // row pass: 8 threads per row, write C
#pragma unroll
        for (int it = 0; it < 4; it++) {
            int r = it * 32 + (tid >> 3);
            int grow = row0 + r;
            if (grow < NN) {
                float* cp = C + (size_t)grow * HH;
#pragma unroll
                for (int j = 0; j < 4; j++) {
                    int c4 = (tid & 7) + j * 8;
                    *(float4*)(cp + c4 * 4) = *(float4*)&sm[r * 132 + c4 * 4];
                }
            }
        }
        if (MODE == 1 && tid < 128) {
            // column pass: thread = column
            float s = 0.f, sq = 0.f;
            int rmax = NN - row0; if (rmax > 128) rmax = 128;
            for (int r = 0; r < rmax; r++) {
                float v = sm[r * 132 + tid];
                s += v; sq += v * v;
            }
            atomicAdd(&g_colsum[tid], s);
            atomicAdd(&g_colsq[tid], sq);
        }
    } else {
        if (tid < 128) {
            int grow = row0 + tid;
            if (grow < NN) {
                float* hp = C + (size_t)grow * HH;
                float s = 0.f, sq = 0.f;
#pragma unroll
                for (int j = 0; j < 32; j++) {
                    float4 o = *(float4*)&sm[tid * 132 + j * 4];
                    float4 hv = *(float4*)(hp + j * 4);
                    float t0 = hv.x + fmaxf(o.x, 0.f);
                    float t1 = hv.y + fmaxf(o.y, 0.f);
                    float t2 = hv.z + fmaxf(o.z, 0.f);
                    float t3 = hv.w + fmaxf(o.w, 0.f);
                    s += t0 + t1 + t2 + t3;
                    sq += t0 * t0 + t1 * t1 + t2 * t2 + t3 * t3;
                }
                float mean = s * (1.0f / 128.0f);
                float var = sq * (1.0f / 128.0f) - mean * mean;
                float rr = rsqrtf(var + 1e-5f);
#pragma unroll
                for (int j = 0; j < 32; j++) {
                    float4 o = *(float4*)&sm[tid * 132 + j * 4];
                    float4 hv = *(float4*)(hp + j * 4);
                    float4 lg = *(float4*)&sm[F_LNG + j * 4];
                    float4 lb = *(float4*)&sm[F_LNB + j * 4];
                    float4 w;
                    w.x = (hv.x + fmaxf(o.x, 0.f) - mean) * rr * lg.x + lb.x;
                    w.y = (hv.y + fmaxf(o.y, 0.f) - mean) * rr * lg.y + lb.y;
                    w.z = (hv.z + fmaxf(o.z, 0.f) - mean) * rr * lg.z + lb.z;
                    w.w = (hv.w + fmaxf(o.w, 0.f) - mean) * rr * lg.w + lb.w;
                    *(float4*)(hp + j * 4) = w;
                }
            }
        }
    }
}

// ------------------ weight transpose + bf16 split (once per launch) ------------------
__global__ void transposek(const float* __restrict__ W0, const float* __restrict__ W1,
                           const float* __restrict__ W2) {
    int i = blockIdx.x * 256 + threadIdx.x;
    if (i >= 9 * HH * HH) return;
    int s = i >> 14, r = i & 16383;
    int n = r >> 7, k = r & 127;
    const float* src = (s == 0) ? W0 : (s < 5 ? W1 + (s - 1) * HH * HH : W2 + (s - 5) * HH * HH);
    float x = __ldg(src + k * HH + n);
    __nv_bfloat16 hb = __float2bfloat16_rn(x);
    float hi = __bfloat162float(hb);
    __nv_bfloat16 lb = __float2bfloat16_rn(x - hi);
    g_wthi[i] = *(u16*)&hb;
    g_wtlo[i] = *(u16*)&lb;
}

// ------------------ graph preprocessing ------------------
__global__ void initk() {
    int i = blockIdx.x * blockDim.x + threadIdx.x;
    if (i < NN) g_deg[i] = 0;
    if (i < GG * HH) g_pool[i] = 0.f;
    if (i < GG) g_cnt[i] = 0.f;
    if (i < HH) { g_colsum[i] = 0.f; g_colsq[i] = 0.f; }
}

__global__ void degk(const int* __restrict__ ei) {
    int e = blockIdx.x * blockDim.x + threadIdx.x;
    if (e >= EE) return;
    int r = ei[e], c = ei[EE + e];
    if (r != c) { atomicAdd(&g_deg[r], 1); atomicAdd(&g_deg[c], 1); }
}

__global__ void scan1k() {
    int b = blockIdx.x, t = threadIdx.x;
    int i = b * 1024 + t;
    int lane = t & 31, wid = t >> 5;
    __shared__ int wsumS[32];
    int v = (i < NN) ? g_deg[i] : 0;
    int x = v;
#pragma unroll
    for (int d = 1; d < 32; d <<= 1) {
        int y = __shfl_up_sync(0xFFFFFFFFu, x, d);
        if (lane >= d) x += y;
    }
    if (lane == 31) wsumS[wid] = x;
    __syncthreads();
    if (wid == 0) {
        int w = wsumS[lane];
#pragma unroll
        for (int d = 1; d < 32; d <<= 1) {
            int y = __shfl_up_sync(0xFFFFFFFFu, w, d);
            if (lane >= d) w += y;
        }
        wsumS[lane] = w;
    }
    __syncthreads();
    int excl = (wid > 0 ? wsumS[wid - 1] : 0) + x - v;
    if (i < NN) g_rowptr[i] = excl;
    if (t == 1023) g_bsum[b] = excl + v;
}

__global__ void scan2k(int nblk) {
    int t = threadIdx.x;
    __shared__ int s[128];
    int v = (t < nblk) ? g_bsum[t] : 0;
    s[t] = v;
    __syncthreads();
    for (int d = 1; d < 128; d <<= 1) {
        int y = 0;
        if (t >= d) y = s[t - d];
        __syncthreads();
        if (t >= d) s[t] += y;
        __syncthreads();
    }
    g_boff[t] = s[t] - v;
    if (t == 127) g_rowptr[NN] = s[127];
}

__global__ void scan3k() {
    int i = blockIdx.x * 1024 + threadIdx.x;
    if (i < NN) {
        int r = g_rowptr[i] + g_boff[blockIdx.x];
        g_rowptr[i] = r;
        g_cur[i] = r;
    }
}

__global__ void fillk(const int* __restrict__ ei) {
    int e = blockIdx.x * blockDim.x + threadIdx.x;
    if (e >= EE) return;
    int r = ei[e], c = ei[EE + e];
    if (r != c) {
        int p = atomicAdd(&g_cur[r], 1); g_colidx[p] = c;
        int q = atomicAdd(&g_cur[c], 1); g_colidx[q] = r;
    }
}

// ------------------ GIN aggregation: one warp per node ------------------
__global__ void aggk(const float* __restrict__ h, float* __restrict__ u,
                     const float* __restrict__ eps_l, int layer) {
    int w = (blockIdx.x * blockDim.x + threadIdx.x) >> 5;
    if (w >= NN) return;
    int lane = threadIdx.x & 31;
    float e1 = 1.0f + __ldg(eps_l + layer);
    const float4* hp = (const float4*)h;
    float4 a = __ldg(hp + (size_t)w * 32 + lane);
    float4 acc = make_float4(a.x * e1, a.y * e1, a.z * e1, a.w * e1);
    int beg = g_rowptr[w], end = g_rowptr[w + 1];
    for (int e = beg; e < end; e++) {
        int nb = g_colidx[e];
        float4 v = __ldg(hp + (size_t)nb * 32 + lane);
        acc.x += v.x; acc.y += v.y; acc.z += v.z; acc.w += v.w;
    }
    ((float4*)u)[(size_t)w * 32 + lane] = acc;
}

// ------------------ BN parameter fold (and reset stats) ------------------
__global__ void bnparamsk(const float* __restrict__ bng, const float* __restrict__ bnb) {
    int f = threadIdx.x;
    float m = g_colsum[f] * (1.0f / NN);
    float v = g_colsq[f] * (1.0f / NN) - m * m;
    float sc = __ldg(bng + f) * rsqrtf(v + 1e-5f);
    g_bnscale[f] = sc;
    g_bnshift[f] = __ldg(bnb + f) - m * sc;
    g_colsum[f] = 0.f;
    g_colsq[f] = 0.f;
}

// ------------------ pooling (batch is sorted) ------------------
__global__ void poolk(const float* __restrict__ h, const int* __restrict__ batch) {
    int f = threadIdx.x;
    int chunk = (NN + gridDim.x - 1) / gridDim.x;
    int s = blockIdx.x * chunk;
    int e = s + chunk; if (e > NN) e = NN;
    if (s >= e) return;
    int g = __ldg(batch + s);
    float acc = 0.f, cnt = 0.f;
    for (int n = s; n < e; n++) {
        int bg = __ldg(batch + n);
        if (bg != g) {
            atomicAdd(&g_pool[g * HH + f], acc);
            if (f == 0) atomicAdd(&g_cnt[g], cnt);
            acc = 0.f; cnt = 0.f; g = bg;
        }
        acc += h[(size_t)n * HH + f];
        cnt += 1.f;
    }
    atomicAdd(&g_pool[g * HH + f], acc);
    if (f == 0) atomicAdd(&g_cnt[g], cnt);
}

__global__ void finalk(float* __restrict__ out) {
    int i = blockIdx.x * blockDim.x + threadIdx.x;
    if (i < GG * HH) {
        float c = g_cnt[i >> 7];
        out[i] = g_pool[i] / fmaxf(c, 1.0f);
    }
}

// ------------------ host launcher ------------------
extern "C" void kernel_launch(void* const* d_in, const int* in_sizes, int n_in,
                              void* d_out, int out_size) {
    const float* x     = (const float*)d_in[0];
    const float* W0    = (const float*)d_in[1];
    const float* b0    = (const float*)d_in[2];
    const float* eps_l = (const float*)d_in[3];
    const float* W1    = (const float*)d_in[4];
    const float* b1    = (const float*)d_in[5];
    const float* bng   = (const float*)d_in[6];
    const float* bnb   = (const float*)d_in[7];
    const float* W2    = (const float*)d_in[8];
    const float* b2    = (const float*)d_in[9];
    const float* lng   = (const float*)d_in[10];
    const float* lnb   = (const float*)d_in[11];
    const int*   ei    = (const int*)d_in[12];
    const int*   batch = (const int*)d_in[13];
    float* out = (float*)d_out;

    cudaFuncSetAttribute((const void*)gemm_hmma<0>, cudaFuncAttributeMaxDynamicSharedMemorySize, SMEM_HM);
    cudaFuncSetAttribute((const void*)gemm_hmma<1>, cudaFuncAttributeMaxDynamicSharedMemorySize, SMEM_HM);
    cudaFuncSetAttribute((const void*)gemm_hmma<2>, cudaFuncAttributeMaxDynamicSharedMemorySize, SMEM_HM);

    float *ph, *pu, *pz;
    u16 *pwh, *pwl;
    cudaGetSymbolAddress((void**)&ph, g_h);
    cudaGetSymbolAddress((void**)&pu, g_u);
    cudaGetSymbolAddress((void**)&pz, g_z);
    cudaGetSymbolAddress((void**)&pwh, g_wthi);
    cudaGetSymbolAddress((void**)&pwl, g_wtlo);

    const int NB = (NN + 1023) / 1024;   // 98
    const int GB = (NN + 127) / 128;     // 782

    initk<<<(NN + 255) / 256, 256>>>();
    transposek<<<(9 * HH * HH + 255) / 256, 256>>>(W0, W1, W2);
    degk<<<(EE + 255) / 256, 256>>>(ei);
    scan1k<<<NB, 1024>>>();
    scan2k<<<1, 128>>>(NB);
    scan3k<<<NB, 1024>>>();
    fillk<<<(EE + 255) / 256, 256>>>(ei);

    gemm_hmma<0><<<GB, 256, SMEM_HM>>>(x, pwh, pwl, b0, ph, nullptr, nullptr);

    for (int i = 0; i < LL; i++) {
        aggk<<<(NN * 32 + 255) / 256, 256>>>(ph, pu, eps_l, i);
        gemm_hmma<1><<<GB, 256, SMEM_HM>>>(pu, pwh + (1 + i) * HH * HH, pwl + (1 + i) * HH * HH,
                                           b1 + i * HH, pz, nullptr, nullptr);
        bnparamsk<<<1, 128>>>(bng + i * HH, bnb + i * HH);
        gemm_hmma<2><<<GB, 256, SMEM_HM>>>(pz, pwh + (5 + i) * HH * HH, pwl + (5 + i) * HH * HH,
                                           b2 + i * HH, ph, lng + i * HH, lnb + i * HH);
    }

    poolk<<<500, 128>>>(ph, batch);
    finalk<<<(GG * HH + 255) / 256, 256>>>(out);
}